// round 12
// baseline (speedup 1.0000x reference)
#include <cuda_runtime.h>
#include <cuda_bf16.h>
#include <cstdint>

#define BB 16
#define NN 2048
#define DD 64
// All bf16 tiles: exact 128-byte rows, XOR swizzle (unit ^= row&7).

// ---------------- scratch (__device__ globals) -----------------------------
__device__ __nv_bfloat16 g_yh[BB * NN * DD];   // normalized x, bf16 hi
__device__ __nv_bfloat16 g_yl[BB * NN * DD];   // normalized x, bf16 lo
__device__ __nv_bfloat16 g_vh[BB * NN * DD];   // support = x@W, bf16 hi
__device__ __nv_bfloat16 g_vl[BB * NN * DD];   // support = x@W, bf16 lo
__device__ float         g_A[NN * NN];         // att * mask

// ---------------- smem byte offsets (swizzled 128B-row tiles) --------------
#define OFF_YNH 0          // 128 x 128B                16384
#define OFF_YNL 16384      //                           16384
#define OFF_YMH 32768      // 2 bufs x (64 x 128B)      16384
#define OFF_YML 49152      //                           16384
#define OFF_VH  65536      // 2 bufs x (64 x 128B)      16384
#define OFF_VL  81920      //                           16384
#define SMEM_BYTES 98304
// epilogue reduction buffer aliases offset 0: 128 x 66 f32 = 33792 B

typedef unsigned long long ull;
__device__ __forceinline__ void unpk(ull v, float& lo, float& hi) {
    asm("mov.b64 {%0, %1}, %2;" : "=f"(lo), "=f"(hi) : "l"(v));
}
__device__ __forceinline__ uint32_t su32(const void* p) {
    uint32_t a;
    asm("{ .reg .u64 t; cvta.to.shared.u64 t, %1; cvt.u32.u64 %0, t; }" : "=r"(a) : "l"(p));
    return a;
}
__device__ __forceinline__ uint32_t swu(uint32_t base, int row, int unit) {
    return base + row * 128 + ((unit ^ (row & 7)) << 4);
}
__device__ __forceinline__ void cpa16(uint32_t dst, const void* src) {
    asm volatile("cp.async.cg.shared.global [%0], [%1], 16;" :: "r"(dst), "l"(src));
}
#define CPA_COMMIT() asm volatile("cp.async.commit_group;" ::: "memory")
#define CPA_WAIT(N)  asm volatile("cp.async.wait_group %0;" :: "n"(N) : "memory")

__device__ __forceinline__ uint32_t pack_bf16(float a, float b) {
    __nv_bfloat162 h = __float22bfloat162_rn(make_float2(a, b));
    return *reinterpret_cast<uint32_t*>(&h);
}

#define LDMX4(r, addr)                                                        \
    asm volatile("ldmatrix.sync.aligned.m8n8.x4.shared.b16 {%0,%1,%2,%3}, [%4];" \
        : "=r"((r)[0]), "=r"((r)[1]), "=r"((r)[2]), "=r"((r)[3]) : "r"(addr))
#define LDMX4_T(r, addr)                                                      \
    asm volatile("ldmatrix.sync.aligned.m8n8.x4.trans.shared.b16 {%0,%1,%2,%3}, [%4];" \
        : "=r"((r)[0]), "=r"((r)[1]), "=r"((r)[2]), "=r"((r)[3]) : "r"(addr))
#define MMA_BF16(c, a, b0, b1)                                                \
    asm volatile("mma.sync.aligned.m16n8k16.row.col.f32.bf16.bf16.f32 "       \
        "{%0,%1,%2,%3}, {%4,%5,%6,%7}, {%8,%9}, {%0,%1,%2,%3};"               \
        : "+f"((c)[0]), "+f"((c)[1]), "+f"((c)[2]), "+f"((c)[3])              \
        : "r"((a)[0]), "r"((a)[1]), "r"((a)[2]), "r"((a)[3]), "r"(b0), "r"(b1))

// ---------------------------------------------------------------------------
// Kernel A: A = att * mask
// ---------------------------------------------------------------------------
__global__ void prep_A(const float* __restrict__ att, const int* __restrict__ mask) {
    int i = blockIdx.x * blockDim.x + threadIdx.x;
    float4 a = reinterpret_cast<const float4*>(att)[i];
    int4   m = reinterpret_cast<const int4*>(mask)[i];
    float4 r;
    r.x = a.x * (float)m.x; r.y = a.y * (float)m.y;
    r.z = a.z * (float)m.z; r.w = a.w * (float)m.w;
    reinterpret_cast<float4*>(g_A)[i] = r;
}

// ---------------------------------------------------------------------------
// Kernel B: y = x/||x|| -> bf16 hi/lo ; v = x @ W -> bf16 hi/lo
// ---------------------------------------------------------------------------
__global__ void prep_xw(const float* __restrict__ x, const float* __restrict__ w) {
    __shared__ float sw[DD * DD];
    int tid = threadIdx.x;
    for (int i = tid; i < DD * DD; i += 256) sw[i] = w[i];
    __syncthreads();

    int warp = tid >> 5, lane = tid & 31;
    int row = blockIdx.x * 8 + warp;
    const float* xr = x + (size_t)row * DD;
    float x0 = xr[lane], x1 = xr[lane + 32];

    float ss = x0 * x0 + x1 * x1;
    #pragma unroll
    for (int o = 16; o; o >>= 1) ss += __shfl_xor_sync(0xffffffffu, ss, o);
    float inv = rsqrtf(fmaxf(ss, 1e-30f));

    float y0 = x0 * inv, y1 = x1 * inv;
    __nv_bfloat16 h0 = __float2bfloat16(y0), h1 = __float2bfloat16(y1);
    size_t rb = (size_t)row * DD;
    g_yh[rb + lane]      = h0;
    g_yh[rb + lane + 32] = h1;
    g_yl[rb + lane]      = __float2bfloat16(y0 - __bfloat162float(h0));
    g_yl[rb + lane + 32] = __float2bfloat16(y1 - __bfloat162float(h1));

    float a0 = 0.f, a1 = 0.f;
    #pragma unroll
    for (int d = 0; d < 32; ++d) {
        float xd = __shfl_sync(0xffffffffu, x0, d);
        a0 = fmaf(xd, sw[d * DD + lane],      a0);
        a1 = fmaf(xd, sw[d * DD + lane + 32], a1);
    }
    #pragma unroll
    for (int d = 0; d < 32; ++d) {
        float xd = __shfl_sync(0xffffffffu, x1, d);
        a0 = fmaf(xd, sw[(d + 32) * DD + lane],      a0);
        a1 = fmaf(xd, sw[(d + 32) * DD + lane + 32], a1);
    }
    __nv_bfloat16 v0 = __float2bfloat16(a0), v1 = __float2bfloat16(a1);
    g_vh[rb + lane]      = v0;
    g_vh[rb + lane + 32] = v1;
    g_vl[rb + lane]      = __float2bfloat16(a0 - __bfloat162float(v0));
    g_vl[rb + lane + 32] = __float2bfloat16(a1 - __bfloat162float(v1));
}

// ---------------------------------------------------------------------------
// Kernel C: register-resident P pipeline.
//   Warp (wn,wm): S(32n x 32m) via bf16-split mma -> P = A*S packed to bf16
//   hi/lo A-FRAGMENTS in registers -> partial O(32n x 64e) over k = own 32m.
//   One __syncthreads per chunk; Ym & V double-buffered via cp.async.
//   Epilogue: wm=1 partials reduced into wm=0 via smem, + bias, store.
// ---------------------------------------------------------------------------
__global__ __launch_bounds__(256, 2)
void fused(const float* __restrict__ bias, float* __restrict__ out) {
    extern __shared__ char smc[];
    uint32_t sb = su32(smc);

    int b  = blockIdx.y;
    int n0 = blockIdx.x * 128;
    int tid = threadIdx.x;
    int w = tid >> 5, lane = tid & 31;
    int wn = w & 3, wm = w >> 2;
    int n0w = wn * 32, m0w = wm * 32;

    const __nv_bfloat16* yhB = g_yh + (size_t)b * NN * DD;
    const __nv_bfloat16* ylB = g_yl + (size_t)b * NN * DD;
    const __nv_bfloat16* vhB = g_vh + (size_t)b * NN * DD;
    const __nv_bfloat16* vlB = g_vl + (size_t)b * NN * DD;

    int sr_base = tid >> 3, sc = tid & 7;

    // Stage Yn tile (128 x 64 bf16 hi/lo), one-time, swizzled
    #pragma unroll
    for (int k = 0; k < 4; ++k) {
        int r = sr_base + k * 32;
        uint32_t dof = swu(0, r, sc);
        size_t gof = (size_t)(n0 + r) * DD + sc * 8;
        *reinterpret_cast<uint4*>(smc + OFF_YNH + dof) =
            *reinterpret_cast<const uint4*>(yhB + gof);
        *reinterpret_cast<uint4*>(smc + OFF_YNL + dof) =
            *reinterpret_cast<const uint4*>(ylB + gof);
    }

    // Prologue: async-stage Ym(0) + V(0) into buf 0
    #pragma unroll
    for (int k = 0; k < 2; ++k) {
        int r = sr_base + k * 32;
        uint32_t dof = swu(0, r, sc);
        size_t gof = (size_t)r * DD + sc * 8;
        cpa16(sb + OFF_YMH + dof, yhB + gof);
        cpa16(sb + OFF_YML + dof, ylB + gof);
        cpa16(sb + OFF_VH + dof, vhB + gof);
        cpa16(sb + OFF_VL + dof, vlB + gof);
    }
    CPA_COMMIT();

    // ldmatrix lane addressing
    int lrow = lane & 7, sub = lane >> 3;
    int rowoff = (sub & 1) * 8 + lrow;
    int usub   = sub >> 1;
    int t4 = lane >> 2, tm2 = (lane & 3) * 2;

    float ofr[2][8][4];          // partial O: [n16 group i][e8 tile][4]
    #pragma unroll
    for (int i = 0; i < 2; ++i)
        #pragma unroll
        for (int te = 0; te < 8; ++te)
            #pragma unroll
            for (int q = 0; q < 4; ++q) ofr[i][te][q] = 0.f;

    for (int c = 0; c < 32; ++c) {
        int m0 = c * 64;
        int buf = c & 1;
        uint32_t bo = (uint32_t)(buf * 8192);

        CPA_WAIT(0);          // chunk c's Ym+V landed
        __syncthreads();      // visible to all; prev chunk's readers done

        // Issue chunk c+1 staging into the other buffer
        if (c + 1 < 32) {
            uint32_t nbo = (uint32_t)((buf ^ 1) * 8192);
            #pragma unroll
            for (int k = 0; k < 2; ++k) {
                int r = sr_base + k * 32;
                uint32_t dof = swu(0, r, sc);
                size_t gof = (size_t)(m0 + 64 + r) * DD + sc * 8;
                cpa16(sb + OFF_YMH + nbo + dof, yhB + gof);
                cpa16(sb + OFF_YML + nbo + dof, ylB + gof);
                cpa16(sb + OFF_VH + nbo + dof, vhB + gof);
                cpa16(sb + OFF_VL + nbo + dof, vlB + gof);
            }
            CPA_COMMIT();
        }

        // ---- S-phase: tensor mma, bf16 split (HH + HL + LH) ----
        float cfr[2][4][4];
        #pragma unroll
        for (int i = 0; i < 2; ++i)
            #pragma unroll
            for (int j = 0; j < 4; ++j)
                #pragma unroll
                for (int q = 0; q < 4; ++q) cfr[i][j][q] = 0.f;

        #pragma unroll
        for (int ks = 0; ks < 4; ++ks) {
            int un = ks * 2 + usub;
            uint32_t aH[2][4], aL[2][4];
            #pragma unroll
            for (int i = 0; i < 2; ++i) {
                uint32_t ra = swu(0, n0w + i * 16 + rowoff, un);
                LDMX4(aH[i], sb + OFF_YNH + ra);
                LDMX4(aL[i], sb + OFF_YNL + ra);
            }
            #pragma unroll
            for (int j16 = 0; j16 < 2; ++j16) {
                uint32_t rb2 = swu(0, m0w + j16 * 16 + rowoff, un);
                uint32_t bH[4], bL[4];
                LDMX4(bH, sb + OFF_YMH + bo + rb2);
                LDMX4(bL, sb + OFF_YML + bo + rb2);
                #pragma unroll
                for (int i = 0; i < 2; ++i)
                    #pragma unroll
                    for (int par = 0; par < 2; ++par) {
                        int mt = j16 * 2 + par;
                        MMA_BF16(cfr[i][mt], aH[i], bH[par], bH[par + 2]);
                        MMA_BF16(cfr[i][mt], aH[i], bL[par], bL[par + 2]);
                        MMA_BF16(cfr[i][mt], aL[i], bH[par], bH[par + 2]);
                    }
            }
        }

        // ---- P-phase (in registers): P = A*S -> bf16 hi/lo A-fragments ----
        uint32_t pfH[2][2][4], pfL[2][2][4];   // [i][kt][frag reg]
        #pragma unroll
        for (int i = 0; i < 2; ++i) {
            #pragma unroll
            for (int mt = 0; mt < 4; ++mt) {
                int kt = mt >> 1, half = (mt & 1) * 2;
                int nfl = n0w + i * 16 + t4;
                int mfl = m0w + mt * 8 + tm2;
                const float* ar = g_A + (size_t)(n0 + nfl) * NN + (m0 + mfl);
                ull ap0 = *reinterpret_cast<const ull*>(ar);
                ull ap1 = *reinterpret_cast<const ull*>(ar + 8 * NN);
                float a0, a1, a2, a3;
                unpk(ap0, a0, a1);
                unpk(ap1, a2, a3);
                float p0 = cfr[i][mt][0] * a0, p1 = cfr[i][mt][1] * a1;
                float p2 = cfr[i][mt][2] * a2, p3 = cfr[i][mt][3] * a3;

                uint32_t h01 = pack_bf16(p0, p1);
                uint32_t h23 = pack_bf16(p2, p3);
                __nv_bfloat162 hb01 = *reinterpret_cast<__nv_bfloat162*>(&h01);
                __nv_bfloat162 hb23 = *reinterpret_cast<__nv_bfloat162*>(&h23);
                float2 f01 = __bfloat1622float2(hb01);
                float2 f23 = __bfloat1622float2(hb23);
                pfH[i][kt][half]     = h01;
                pfH[i][kt][half + 1] = h23;
                pfL[i][kt][half]     = pack_bf16(p0 - f01.x, p1 - f01.y);
                pfL[i][kt][half + 1] = pack_bf16(p2 - f23.x, p3 - f23.y);
            }
        }

        // ---- O-phase: partial O(32n x 64e) over k = warp's 32 m ----
        #pragma unroll
        for (int kt = 0; kt < 2; ++kt) {
            #pragma unroll
            for (int eg = 0; eg < 4; ++eg) {
                uint32_t va = swu(0, m0w + kt * 16 + rowoff, eg * 2 + usub);
                uint32_t vH[4], vL[4];
                LDMX4_T(vH, sb + OFF_VH + bo + va);
                LDMX4_T(vL, sb + OFF_VL + bo + va);
                #pragma unroll
                for (int i = 0; i < 2; ++i) {
                    MMA_BF16(ofr[i][eg * 2],     pfH[i][kt], vH[0], vH[1]);
                    MMA_BF16(ofr[i][eg * 2],     pfH[i][kt], vL[0], vL[1]);
                    MMA_BF16(ofr[i][eg * 2],     pfL[i][kt], vH[0], vH[1]);
                    MMA_BF16(ofr[i][eg * 2 + 1], pfH[i][kt], vH[2], vH[3]);
                    MMA_BF16(ofr[i][eg * 2 + 1], pfH[i][kt], vL[2], vL[3]);
                    MMA_BF16(ofr[i][eg * 2 + 1], pfL[i][kt], vH[2], vH[3]);
                }
            }
        }
    }

    // ---- Epilogue: reduce wm=1 partials into wm=0, + bias, store ----
    __syncthreads();                          // all tile reads done; reuse smem
    float* red = reinterpret_cast<float*>(smc);   // [128][66]
    if (wm == 1) {
        #pragma unroll
        for (int i = 0; i < 2; ++i) {
            int r = wn * 32 + i * 16 + t4;
            #pragma unroll
            for (int te = 0; te < 8; ++te) {
                int e = te * 8 + tm2;
                *reinterpret_cast<float2*>(red + r * 66 + e) =
                    make_float2(ofr[i][te][0], ofr[i][te][1]);
                *reinterpret_cast<float2*>(red + (r + 8) * 66 + e) =
                    make_float2(ofr[i][te][2], ofr[i][te][3]);
            }
        }
    }
    __syncthreads();
    if (wm == 0) {
        float* ob = out + ((size_t)b * NN + n0) * DD;
        #pragma unroll
        for (int i = 0; i < 2; ++i) {
            int r = wn * 32 + i * 16 + t4;
            #pragma unroll
            for (int te = 0; te < 8; ++te) {
                int e = te * 8 + tm2;
                float bj0 = bias[e], bj1 = bias[e + 1];
                float2 q0 = *reinterpret_cast<float2*>(red + r * 66 + e);
                float2 q1 = *reinterpret_cast<float2*>(red + (r + 8) * 66 + e);
                *reinterpret_cast<float2*>(ob + (size_t)r * DD + e) =
                    make_float2(ofr[i][te][0] + q0.x + bj0, ofr[i][te][1] + q0.y + bj1);
                *reinterpret_cast<float2*>(ob + (size_t)(r + 8) * DD + e) =
                    make_float2(ofr[i][te][2] + q1.x + bj0, ofr[i][te][3] + q1.y + bj1);
            }
        }
    }
}

// ---------------------------------------------------------------------------
extern "C" void kernel_launch(void* const* d_in, const int* in_sizes, int n_in,
                              void* d_out, int out_size) {
    const float* x    = (const float*)d_in[0];
    const float* w    = (const float*)d_in[1];
    const float* att  = (const float*)d_in[2];
    const float* bias = (const float*)d_in[3];
    const int*   mask = (const int*)d_in[4];
    float* out = (float*)d_out;

    prep_A<<<(NN * NN / 4) / 256, 256>>>(att, mask);
    prep_xw<<<(BB * NN) / 8, 256>>>(x, w);

    cudaFuncSetAttribute(fused, cudaFuncAttributeMaxDynamicSharedMemorySize, SMEM_BYTES);
    dim3 grid(NN / 128, BB);
    fused<<<grid, 256, SMEM_BYTES>>>(bias, out);
}

// round 13
// speedup vs baseline: 1.2505x; 1.2505x over previous
#include <cuda_runtime.h>
#include <cuda_bf16.h>
#include <cuda_fp16.h>
#include <cstdint>

#define BB 16
#define NN 2048
#define DD 64
// All 16-bit tiles: exact 128-byte rows, XOR swizzle (unit ^= row&7).

// ---------------- scratch (__device__ globals) -----------------------------
__device__ __nv_bfloat16 g_yh[BB * NN * DD];   // normalized x, bf16 hi
__device__ __nv_bfloat16 g_yl[BB * NN * DD];   // normalized x, bf16 lo
__device__ __half        g_v[BB * NN * DD];    // support = x@W, fp16
__device__ float         g_A[NN * NN];         // att * mask

// ---------------- smem byte offsets (swizzled 128B-row tiles) --------------
#define OFF_YNH 0          // 128 x 128B                16384
#define OFF_YNL 16384      //                           16384
#define OFF_YMH 32768      // 2 bufs x (64 x 128B)      16384
#define OFF_YML 49152      //                           16384
#define OFF_V   65536      // 2 bufs x (64 x 128B)      16384
#define OFF_PH  81920      // 128 x 128B (fp16)         16384
#define OFF_PL  98304      //                           16384
#define SMEM_BYTES 114688

typedef unsigned long long ull;
__device__ __forceinline__ void unpk(ull v, float& lo, float& hi) {
    asm("mov.b64 {%0, %1}, %2;" : "=f"(lo), "=f"(hi) : "l"(v));
}
__device__ __forceinline__ uint32_t su32(const void* p) {
    uint32_t a;
    asm("{ .reg .u64 t; cvta.to.shared.u64 t, %1; cvt.u32.u64 %0, t; }" : "=r"(a) : "l"(p));
    return a;
}
__device__ __forceinline__ uint32_t swu(uint32_t base, int row, int unit) {
    return base + row * 128 + ((unit ^ (row & 7)) << 4);
}
__device__ __forceinline__ void cpa16(uint32_t dst, const void* src) {
    asm volatile("cp.async.cg.shared.global [%0], [%1], 16;" :: "r"(dst), "l"(src));
}
#define CPA_COMMIT() asm volatile("cp.async.commit_group;" ::: "memory")
#define CPA_WAIT(N)  asm volatile("cp.async.wait_group %0;" :: "n"(N) : "memory")

#define LDMX4(r, addr)                                                        \
    asm volatile("ldmatrix.sync.aligned.m8n8.x4.shared.b16 {%0,%1,%2,%3}, [%4];" \
        : "=r"((r)[0]), "=r"((r)[1]), "=r"((r)[2]), "=r"((r)[3]) : "r"(addr))
#define LDMX4_T(r, addr)                                                      \
    asm volatile("ldmatrix.sync.aligned.m8n8.x4.trans.shared.b16 {%0,%1,%2,%3}, [%4];" \
        : "=r"((r)[0]), "=r"((r)[1]), "=r"((r)[2]), "=r"((r)[3]) : "r"(addr))
#define MMA_BF16(c, a, b0, b1)                                                \
    asm volatile("mma.sync.aligned.m16n8k16.row.col.f32.bf16.bf16.f32 "       \
        "{%0,%1,%2,%3}, {%4,%5,%6,%7}, {%8,%9}, {%0,%1,%2,%3};"               \
        : "+f"((c)[0]), "+f"((c)[1]), "+f"((c)[2]), "+f"((c)[3])              \
        : "r"((a)[0]), "r"((a)[1]), "r"((a)[2]), "r"((a)[3]), "r"(b0), "r"(b1))
#define MMA_F16(c, a, b0, b1)                                                 \
    asm volatile("mma.sync.aligned.m16n8k16.row.col.f32.f16.f16.f32 "         \
        "{%0,%1,%2,%3}, {%4,%5,%6,%7}, {%8,%9}, {%0,%1,%2,%3};"               \
        : "+f"((c)[0]), "+f"((c)[1]), "+f"((c)[2]), "+f"((c)[3])              \
        : "r"((a)[0]), "r"((a)[1]), "r"((a)[2]), "r"((a)[3]), "r"(b0), "r"(b1))

// ---------------------------------------------------------------------------
// Kernel A: A = att * mask
// ---------------------------------------------------------------------------
__global__ void prep_A(const float* __restrict__ att, const int* __restrict__ mask) {
    int i = blockIdx.x * blockDim.x + threadIdx.x;
    float4 a = reinterpret_cast<const float4*>(att)[i];
    int4   m = reinterpret_cast<const int4*>(mask)[i];
    float4 r;
    r.x = a.x * (float)m.x; r.y = a.y * (float)m.y;
    r.z = a.z * (float)m.z; r.w = a.w * (float)m.w;
    reinterpret_cast<float4*>(g_A)[i] = r;
}

// ---------------------------------------------------------------------------
// Kernel B: y = x/||x|| -> bf16 hi/lo ; v = x @ W -> fp16
// ---------------------------------------------------------------------------
__global__ void prep_xw(const float* __restrict__ x, const float* __restrict__ w) {
    __shared__ float sw[DD * DD];
    int tid = threadIdx.x;
    for (int i = tid; i < DD * DD; i += 256) sw[i] = w[i];
    __syncthreads();

    int warp = tid >> 5, lane = tid & 31;
    int row = blockIdx.x * 8 + warp;
    const float* xr = x + (size_t)row * DD;
    float x0 = xr[lane], x1 = xr[lane + 32];

    float ss = x0 * x0 + x1 * x1;
    #pragma unroll
    for (int o = 16; o; o >>= 1) ss += __shfl_xor_sync(0xffffffffu, ss, o);
    float inv = rsqrtf(fmaxf(ss, 1e-30f));

    float y0 = x0 * inv, y1 = x1 * inv;
    __nv_bfloat16 h0 = __float2bfloat16(y0), h1 = __float2bfloat16(y1);
    size_t rb = (size_t)row * DD;
    g_yh[rb + lane]      = h0;
    g_yh[rb + lane + 32] = h1;
    g_yl[rb + lane]      = __float2bfloat16(y0 - __bfloat162float(h0));
    g_yl[rb + lane + 32] = __float2bfloat16(y1 - __bfloat162float(h1));

    float a0 = 0.f, a1 = 0.f;
    #pragma unroll
    for (int d = 0; d < 32; ++d) {
        float xd = __shfl_sync(0xffffffffu, x0, d);
        a0 = fmaf(xd, sw[d * DD + lane],      a0);
        a1 = fmaf(xd, sw[d * DD + lane + 32], a1);
    }
    #pragma unroll
    for (int d = 0; d < 32; ++d) {
        float xd = __shfl_sync(0xffffffffu, x1, d);
        a0 = fmaf(xd, sw[(d + 32) * DD + lane],      a0);
        a1 = fmaf(xd, sw[(d + 32) * DD + lane + 32], a1);
    }
    g_v[rb + lane]      = __float2half_rn(a0);
    g_v[rb + lane + 32] = __float2half_rn(a1);
}

// ---------------------------------------------------------------------------
// Kernel C: S = Yn.Ym^T (bf16 3-pass) -> P = A*S -> fp16 hi/lo in smem
//           -> O += P.V (fp16, 2 passes: PhV + PlV; V single fp16).
//   CTA = (b, 128n); 32 chunks of 64 m; Ym + V double-buffered cp.async.
//   2 barriers/chunk. S warp (wn,wm): 32n x 32m. O warp (wn,wm): 32n x 32e.
// ---------------------------------------------------------------------------
__global__ __launch_bounds__(256, 2)
void fused(const float* __restrict__ bias, float* __restrict__ out) {
    extern __shared__ char smc[];
    uint32_t sb = su32(smc);

    int b  = blockIdx.y;
    int n0 = blockIdx.x * 128;
    int tid = threadIdx.x;
    int w = tid >> 5, lane = tid & 31;
    int wn = w & 3, wm = w >> 2;
    int n0w = wn * 32, m0w = wm * 32;

    const __nv_bfloat16* yhB = g_yh + (size_t)b * NN * DD;
    const __nv_bfloat16* ylB = g_yl + (size_t)b * NN * DD;
    const __half*        vB  = g_v  + (size_t)b * NN * DD;

    int sr_base = tid >> 3, sc = tid & 7;

    // Stage Yn tile (128 x 64 bf16 hi/lo), one-time, swizzled
    #pragma unroll
    for (int k = 0; k < 4; ++k) {
        int r = sr_base + k * 32;
        uint32_t dof = swu(0, r, sc);
        size_t gof = (size_t)(n0 + r) * DD + sc * 8;
        *reinterpret_cast<uint4*>(smc + OFF_YNH + dof) =
            *reinterpret_cast<const uint4*>(yhB + gof);
        *reinterpret_cast<uint4*>(smc + OFF_YNL + dof) =
            *reinterpret_cast<const uint4*>(ylB + gof);
    }

    // Prologue: stage chunk 0 into buf 0
    #pragma unroll
    for (int k = 0; k < 2; ++k) {
        int r = sr_base + k * 32;
        uint32_t dof = swu(0, r, sc);
        size_t gof = (size_t)r * DD + sc * 8;
        cpa16(sb + OFF_YMH + dof, yhB + gof);
        cpa16(sb + OFF_YML + dof, ylB + gof);
        cpa16(sb + OFF_V   + dof, vB  + gof);
    }
    CPA_COMMIT();

    // ldmatrix lane addressing
    int lrow = lane & 7, sub = lane >> 3;
    int rowoff = (sub & 1) * 8 + lrow;
    int usub   = sub >> 1;
    int t4 = lane >> 2, tm2 = (lane & 3) * 2;

    float ofr[2][4][4];            // O frags: [n16 group i][e8 tile][4]
    #pragma unroll
    for (int i = 0; i < 2; ++i)
        #pragma unroll
        for (int te = 0; te < 4; ++te)
            #pragma unroll
            for (int q = 0; q < 4; ++q) ofr[i][te][q] = 0.f;

    for (int c = 0; c < 32; ++c) {
        int m0 = c * 64;
        int buf = c & 1;
        uint32_t bo = (uint32_t)(buf * 8192);

        CPA_WAIT(0);          // chunk c tiles landed
        __syncthreads();      // publish; all warps done with prior chunk

        // Issue chunk c+1 staging into the other buffer (safe: behind barrier)
        if (c + 1 < 32) {
            uint32_t nbo = (uint32_t)((buf ^ 1) * 8192);
            #pragma unroll
            for (int k = 0; k < 2; ++k) {
                int r = sr_base + k * 32;
                uint32_t dof = swu(0, r, sc);
                size_t gof = (size_t)(m0 + 64 + r) * DD + sc * 8;
                cpa16(sb + OFF_YMH + nbo + dof, yhB + gof);
                cpa16(sb + OFF_YML + nbo + dof, ylB + gof);
                cpa16(sb + OFF_V   + nbo + dof, vB  + gof);
            }
            CPA_COMMIT();
        }

        // ---- S-phase: tensor mma, bf16 split (HH + HL + LH) ----
        float cfr[2][4][4];
        #pragma unroll
        for (int i = 0; i < 2; ++i)
            #pragma unroll
            for (int j = 0; j < 4; ++j)
                #pragma unroll
                for (int q = 0; q < 4; ++q) cfr[i][j][q] = 0.f;

        #pragma unroll
        for (int ks = 0; ks < 4; ++ks) {
            int un = ks * 2 + usub;
            uint32_t aH[2][4], aL[2][4];
            #pragma unroll
            for (int i = 0; i < 2; ++i) {
                uint32_t ra = swu(0, n0w + i * 16 + rowoff, un);
                LDMX4(aH[i], sb + OFF_YNH + ra);
                LDMX4(aL[i], sb + OFF_YNL + ra);
            }
            #pragma unroll
            for (int j16 = 0; j16 < 2; ++j16) {
                uint32_t rb2 = swu(0, m0w + j16 * 16 + rowoff, un);
                uint32_t bH[4], bL[4];
                LDMX4(bH, sb + OFF_YMH + bo + rb2);
                LDMX4(bL, sb + OFF_YML + bo + rb2);
                #pragma unroll
                for (int i = 0; i < 2; ++i)
                    #pragma unroll
                    for (int par = 0; par < 2; ++par) {
                        int mt = j16 * 2 + par;
                        MMA_BF16(cfr[i][mt], aH[i], bH[par], bH[par + 2]);
                        MMA_BF16(cfr[i][mt], aH[i], bL[par], bL[par + 2]);
                        MMA_BF16(cfr[i][mt], aL[i], bH[par], bH[par + 2]);
                    }
            }
        }

        // ---- P-phase: P = A*S -> fp16 hi/lo into sPh/sPl [n][m] ----
        #pragma unroll
        for (int i = 0; i < 2; ++i) {
            #pragma unroll
            for (int mt = 0; mt < 4; ++mt) {
                int nfl = n0w + i * 16 + t4;
                int mfl = m0w + mt * 8 + tm2;
                const float* ar = g_A + (size_t)(n0 + nfl) * NN + (m0 + mfl);
                ull ap0 = *reinterpret_cast<const ull*>(ar);
                ull ap1 = *reinterpret_cast<const ull*>(ar + 8 * NN);
                float a0, a1, a2, a3;
                unpk(ap0, a0, a1);
                unpk(ap1, a2, a3);
                float p0 = cfr[i][mt][0] * a0, p1 = cfr[i][mt][1] * a1;
                float p2 = cfr[i][mt][2] * a2, p3 = cfr[i][mt][3] * a3;

                int u = mfl >> 3;
                __half2 h01 = __floats2half2_rn(p0, p1);
                float2 f01 = __half22float2(h01);
                __half2 l01 = __floats2half2_rn(p0 - f01.x, p1 - f01.y);
                uint32_t o01 = (uint32_t)(nfl * 128 + ((u ^ (nfl & 7)) << 4) + tm2 * 2);
                *reinterpret_cast<__half2*>(smc + OFF_PH + o01) = h01;
                *reinterpret_cast<__half2*>(smc + OFF_PL + o01) = l01;

                int nf8 = nfl + 8;
                __half2 h23 = __floats2half2_rn(p2, p3);
                float2 f23 = __half22float2(h23);
                __half2 l23 = __floats2half2_rn(p2 - f23.x, p3 - f23.y);
                uint32_t o23 = (uint32_t)(nf8 * 128 + ((u ^ (nf8 & 7)) << 4) + tm2 * 2);
                *reinterpret_cast<__half2*>(smc + OFF_PH + o23) = h23;
                *reinterpret_cast<__half2*>(smc + OFF_PL + o23) = l23;
            }
        }
        __syncthreads();

        // ---- O-phase: fp16 mma, 2 passes (PhV + PlV); warp = 32n x 32e ----
        #pragma unroll
        for (int ks = 0; ks < 4; ++ks) {
            int un = ks * 2 + usub;
            uint32_t pH[2][4], pL[2][4];
            #pragma unroll
            for (int i = 0; i < 2; ++i) {
                uint32_t ra = swu(0, n0w + i * 16 + rowoff, un);
                LDMX4(pH[i], sb + OFF_PH + ra);
                LDMX4(pL[i], sb + OFF_PL + ra);
            }
            #pragma unroll
            for (int egl = 0; egl < 2; ++egl) {
                int eg = wm * 2 + egl;
                uint32_t va = swu(0, ks * 16 + rowoff, eg * 2 + usub);
                uint32_t vv[4];
                LDMX4_T(vv, sb + OFF_V + bo + va);
                #pragma unroll
                for (int i = 0; i < 2; ++i) {
                    MMA_F16(ofr[i][egl * 2],     pH[i], vv[0], vv[1]);
                    MMA_F16(ofr[i][egl * 2],     pL[i], vv[0], vv[1]);
                    MMA_F16(ofr[i][egl * 2 + 1], pH[i], vv[2], vv[3]);
                    MMA_F16(ofr[i][egl * 2 + 1], pL[i], vv[2], vv[3]);
                }
            }
        }
    }

    // ---- Epilogue: direct per-warp stores, + bias ----
    float* ob = out + ((size_t)b * NN + n0) * DD;
    #pragma unroll
    for (int i = 0; i < 2; ++i) {
        int r = wn * 32 + i * 16 + t4;
        #pragma unroll
        for (int te = 0; te < 4; ++te) {
            int e = wm * 32 + te * 8 + tm2;
            float bj0 = bias[e], bj1 = bias[e + 1];
            *reinterpret_cast<float2*>(ob + (size_t)r * DD + e) =
                make_float2(ofr[i][te][0] + bj0, ofr[i][te][1] + bj1);
            *reinterpret_cast<float2*>(ob + (size_t)(r + 8) * DD + e) =
                make_float2(ofr[i][te][2] + bj0, ofr[i][te][3] + bj1);
        }
    }
}

// ---------------------------------------------------------------------------
extern "C" void kernel_launch(void* const* d_in, const int* in_sizes, int n_in,
                              void* d_out, int out_size) {
    const float* x    = (const float*)d_in[0];
    const float* w    = (const float*)d_in[1];
    const float* att  = (const float*)d_in[2];
    const float* bias = (const float*)d_in[3];
    const int*   mask = (const int*)d_in[4];
    float* out = (float*)d_out;

    prep_A<<<(NN * NN / 4) / 256, 256>>>(att, mask);
    prep_xw<<<(BB * NN) / 8, 256>>>(x, w);

    cudaFuncSetAttribute(fused, cudaFuncAttributeMaxDynamicSharedMemorySize, SMEM_BYTES);
    dim3 grid(NN / 128, BB);
    fused<<<grid, 256, SMEM_BYTES>>>(bias, out);
}

// round 14
// speedup vs baseline: 1.3859x; 1.1083x over previous
#include <cuda_runtime.h>
#include <cuda_bf16.h>
#include <cuda_fp16.h>
#include <cstdint>

#define BB 16
#define NN 2048
#define DD 64
// All 16-bit tiles: exact 128-byte rows, XOR swizzle (unit ^= row&7).

// ---------------- scratch (__device__ globals) -----------------------------
__device__ __nv_bfloat16 g_yh[BB * NN * DD];   // normalized x, bf16 hi
__device__ __nv_bfloat16 g_yl[BB * NN * DD];   // normalized x, bf16 lo
__device__ __half        g_v[BB * NN * DD];    // support = x@W, fp16
__device__ float         g_A[NN * NN];         // att * mask

// ---------------- smem byte offsets (swizzled 128B-row tiles) --------------
#define OFF_YNH 0          // 128 x 128B                     16384
#define OFF_YNL 16384      //                                16384
#define OFF_YMH 32768      // 2 bufs x (64 x 128B)           16384
#define OFF_YML 49152      //                                16384
#define OFF_V   65536      // 2 bufs x (64 x 128B, fp16)     16384
#define OFF_PH  81920      // 2 bufs x (128 x 128B, fp16)    32768
#define SMEM_BYTES 114688

typedef unsigned long long ull;
__device__ __forceinline__ void unpk(ull v, float& lo, float& hi) {
    asm("mov.b64 {%0, %1}, %2;" : "=f"(lo), "=f"(hi) : "l"(v));
}
__device__ __forceinline__ uint32_t su32(const void* p) {
    uint32_t a;
    asm("{ .reg .u64 t; cvta.to.shared.u64 t, %1; cvt.u32.u64 %0, t; }" : "=r"(a) : "l"(p));
    return a;
}
__device__ __forceinline__ uint32_t swu(uint32_t base, int row, int unit) {
    return base + row * 128 + ((unit ^ (row & 7)) << 4);
}
__device__ __forceinline__ void cpa16(uint32_t dst, const void* src) {
    asm volatile("cp.async.cg.shared.global [%0], [%1], 16;" :: "r"(dst), "l"(src));
}
#define CPA_COMMIT() asm volatile("cp.async.commit_group;" ::: "memory")
#define CPA_WAIT(N)  asm volatile("cp.async.wait_group %0;" :: "n"(N) : "memory")

#define LDMX4(r, addr)                                                        \
    asm volatile("ldmatrix.sync.aligned.m8n8.x4.shared.b16 {%0,%1,%2,%3}, [%4];" \
        : "=r"((r)[0]), "=r"((r)[1]), "=r"((r)[2]), "=r"((r)[3]) : "r"(addr))
#define LDMX4_T(r, addr)                                                      \
    asm volatile("ldmatrix.sync.aligned.m8n8.x4.trans.shared.b16 {%0,%1,%2,%3}, [%4];" \
        : "=r"((r)[0]), "=r"((r)[1]), "=r"((r)[2]), "=r"((r)[3]) : "r"(addr))
#define MMA_BF16(c, a, b0, b1)                                                \
    asm volatile("mma.sync.aligned.m16n8k16.row.col.f32.bf16.bf16.f32 "       \
        "{%0,%1,%2,%3}, {%4,%5,%6,%7}, {%8,%9}, {%0,%1,%2,%3};"               \
        : "+f"((c)[0]), "+f"((c)[1]), "+f"((c)[2]), "+f"((c)[3])              \
        : "r"((a)[0]), "r"((a)[1]), "r"((a)[2]), "r"((a)[3]), "r"(b0), "r"(b1))
#define MMA_F16(c, a, b0, b1)                                                 \
    asm volatile("mma.sync.aligned.m16n8k16.row.col.f32.f16.f16.f32 "         \
        "{%0,%1,%2,%3}, {%4,%5,%6,%7}, {%8,%9}, {%0,%1,%2,%3};"               \
        : "+f"((c)[0]), "+f"((c)[1]), "+f"((c)[2]), "+f"((c)[3])              \
        : "r"((a)[0]), "r"((a)[1]), "r"((a)[2]), "r"((a)[3]), "r"(b0), "r"(b1))

// ---------------------------------------------------------------------------
// Kernel A: A = att * mask
// ---------------------------------------------------------------------------
__global__ void prep_A(const float* __restrict__ att, const int* __restrict__ mask) {
    int i = blockIdx.x * blockDim.x + threadIdx.x;
    float4 a = reinterpret_cast<const float4*>(att)[i];
    int4   m = reinterpret_cast<const int4*>(mask)[i];
    float4 r;
    r.x = a.x * (float)m.x; r.y = a.y * (float)m.y;
    r.z = a.z * (float)m.z; r.w = a.w * (float)m.w;
    reinterpret_cast<float4*>(g_A)[i] = r;
}

// ---------------------------------------------------------------------------
// Kernel B: y = x/||x|| -> bf16 hi/lo ; v = x @ W -> fp16
// ---------------------------------------------------------------------------
__global__ void prep_xw(const float* __restrict__ x, const float* __restrict__ w) {
    __shared__ float sw[DD * DD];
    int tid = threadIdx.x;
    for (int i = tid; i < DD * DD; i += 256) sw[i] = w[i];
    __syncthreads();

    int warp = tid >> 5, lane = tid & 31;
    int row = blockIdx.x * 8 + warp;
    const float* xr = x + (size_t)row * DD;
    float x0 = xr[lane], x1 = xr[lane + 32];

    float ss = x0 * x0 + x1 * x1;
    #pragma unroll
    for (int o = 16; o; o >>= 1) ss += __shfl_xor_sync(0xffffffffu, ss, o);
    float inv = rsqrtf(fmaxf(ss, 1e-30f));

    float y0 = x0 * inv, y1 = x1 * inv;
    __nv_bfloat16 h0 = __float2bfloat16(y0), h1 = __float2bfloat16(y1);
    size_t rb = (size_t)row * DD;
    g_yh[rb + lane]      = h0;
    g_yh[rb + lane + 32] = h1;
    g_yl[rb + lane]      = __float2bfloat16(y0 - __bfloat162float(h0));
    g_yl[rb + lane + 32] = __float2bfloat16(y1 - __bfloat162float(h1));

    float a0 = 0.f, a1 = 0.f;
    #pragma unroll
    for (int d = 0; d < 32; ++d) {
        float xd = __shfl_sync(0xffffffffu, x0, d);
        a0 = fmaf(xd, sw[d * DD + lane],      a0);
        a1 = fmaf(xd, sw[d * DD + lane + 32], a1);
    }
    #pragma unroll
    for (int d = 0; d < 32; ++d) {
        float xd = __shfl_sync(0xffffffffu, x1, d);
        a0 = fmaf(xd, sw[(d + 32) * DD + lane],      a0);
        a1 = fmaf(xd, sw[(d + 32) * DD + lane + 32], a1);
    }
    g_v[rb + lane]      = __float2half_rn(a0);
    g_v[rb + lane + 32] = __float2half_rn(a1);
}

// ---------------------------------------------------------------------------
// Kernel C: 1-barrier pipelined: iter c does  B1 | stage(c+1) | S(c)+P(c) | O(c-1).
//   sP and V double-buffered; Ym double-buffered. P single-pass fp16.
//   CTA = (b, 128n); 32 chunks of 64 m.
// ---------------------------------------------------------------------------
__global__ __launch_bounds__(256, 2)
void fused(const float* __restrict__ bias, float* __restrict__ out) {
    extern __shared__ char smc[];
    uint32_t sb = su32(smc);

    int b  = blockIdx.y;
    int n0 = blockIdx.x * 128;
    int tid = threadIdx.x;
    int w = tid >> 5, lane = tid & 31;
    int wn = w & 3, wm = w >> 2;
    int n0w = wn * 32, m0w = wm * 32;

    const __nv_bfloat16* yhB = g_yh + (size_t)b * NN * DD;
    const __nv_bfloat16* ylB = g_yl + (size_t)b * NN * DD;
    const __half*        vB  = g_v  + (size_t)b * NN * DD;

    int sr_base = tid >> 3, sc = tid & 7;

    // Stage Yn tile (128 x 64 bf16 hi/lo), one-time, swizzled
    #pragma unroll
    for (int k = 0; k < 4; ++k) {
        int r = sr_base + k * 32;
        uint32_t dof = swu(0, r, sc);
        size_t gof = (size_t)(n0 + r) * DD + sc * 8;
        *reinterpret_cast<uint4*>(smc + OFF_YNH + dof) =
            *reinterpret_cast<const uint4*>(yhB + gof);
        *reinterpret_cast<uint4*>(smc + OFF_YNL + dof) =
            *reinterpret_cast<const uint4*>(ylB + gof);
    }

    // Prologue: async-stage Ym(0) into buf 0
    #pragma unroll
    for (int k = 0; k < 2; ++k) {
        int r = sr_base + k * 32;
        uint32_t dof = swu(0, r, sc);
        size_t gof = (size_t)r * DD + sc * 8;
        cpa16(sb + OFF_YMH + dof, yhB + gof);
        cpa16(sb + OFF_YML + dof, ylB + gof);
    }
    CPA_COMMIT();

    // ldmatrix lane addressing
    int lrow = lane & 7, sub = lane >> 3;
    int rowoff = (sub & 1) * 8 + lrow;
    int usub   = sub >> 1;
    int t4 = lane >> 2, tm2 = (lane & 3) * 2;

    float ofr[2][4][4];            // O frags: [n16 group i][e8 tile][4]
    #pragma unroll
    for (int i = 0; i < 2; ++i)
        #pragma unroll
        for (int te = 0; te < 4; ++te)
            #pragma unroll
            for (int q = 0; q < 4; ++q) ofr[i][te][q] = 0.f;

    for (int c = 0; c <= 32; ++c) {
        int buf = c & 1;

        CPA_WAIT(0);          // group from iter c-1: Ym(c) + V(c-1)
        __syncthreads();

        // Stage Ym(c+1) into buf^1 and V(c) into Vbuf[c&1]
        if (c < 32) {
            #pragma unroll
            for (int k = 0; k < 2; ++k) {
                int r = sr_base + k * 32;
                uint32_t dof = swu(0, r, sc);
                if (c + 1 < 32) {
                    size_t gof = (size_t)((c + 1) * 64 + r) * DD + sc * 8;
                    uint32_t nbo = (uint32_t)((buf ^ 1) * 8192);
                    cpa16(sb + OFF_YMH + nbo + dof, yhB + gof);
                    cpa16(sb + OFF_YML + nbo + dof, ylB + gof);
                }
                size_t gv = (size_t)(c * 64 + r) * DD + sc * 8;
                cpa16(sb + OFF_V + (uint32_t)(buf * 8192) + dof, vB + gv);
            }
            CPA_COMMIT();
        }

        // ---- S(c) + P(c) ----
        if (c < 32) {
            int m0 = c * 64;
            uint32_t bo = (uint32_t)(buf * 8192);

            float cfr[2][4][4];
            #pragma unroll
            for (int i = 0; i < 2; ++i)
                #pragma unroll
                for (int j = 0; j < 4; ++j)
                    #pragma unroll
                    for (int q = 0; q < 4; ++q) cfr[i][j][q] = 0.f;

            #pragma unroll
            for (int ks = 0; ks < 4; ++ks) {
                int un = ks * 2 + usub;
                uint32_t aH[2][4], aL[2][4];
                #pragma unroll
                for (int i = 0; i < 2; ++i) {
                    uint32_t ra = swu(0, n0w + i * 16 + rowoff, un);
                    LDMX4(aH[i], sb + OFF_YNH + ra);
                    LDMX4(aL[i], sb + OFF_YNL + ra);
                }
                #pragma unroll
                for (int j16 = 0; j16 < 2; ++j16) {
                    uint32_t rb2 = swu(0, m0w + j16 * 16 + rowoff, un);
                    uint32_t bH[4], bL[4];
                    LDMX4(bH, sb + OFF_YMH + bo + rb2);
                    LDMX4(bL, sb + OFF_YML + bo + rb2);
                    #pragma unroll
                    for (int i = 0; i < 2; ++i)
                        #pragma unroll
                        for (int par = 0; par < 2; ++par) {
                            int mt = j16 * 2 + par;
                            MMA_BF16(cfr[i][mt], aH[i], bH[par], bH[par + 2]);
                            MMA_BF16(cfr[i][mt], aH[i], bL[par], bL[par + 2]);
                            MMA_BF16(cfr[i][mt], aL[i], bH[par], bH[par + 2]);
                        }
                }
            }

            // P = A*S -> fp16 (single) into sPh buf
            uint32_t pb = (uint32_t)(buf * 16384);
            #pragma unroll
            for (int i = 0; i < 2; ++i) {
                #pragma unroll
                for (int mt = 0; mt < 4; ++mt) {
                    int nfl = n0w + i * 16 + t4;
                    int mfl = m0w + mt * 8 + tm2;
                    const float* ar = g_A + (size_t)(n0 + nfl) * NN + (m0 + mfl);
                    ull ap0 = *reinterpret_cast<const ull*>(ar);
                    ull ap1 = *reinterpret_cast<const ull*>(ar + 8 * NN);
                    float a0, a1, a2, a3;
                    unpk(ap0, a0, a1);
                    unpk(ap1, a2, a3);
                    float p0 = cfr[i][mt][0] * a0, p1 = cfr[i][mt][1] * a1;
                    float p2 = cfr[i][mt][2] * a2, p3 = cfr[i][mt][3] * a3;

                    int u = mfl >> 3;
                    uint32_t o01 = (uint32_t)(nfl * 128 + ((u ^ (nfl & 7)) << 4) + tm2 * 2);
                    *reinterpret_cast<__half2*>(smc + OFF_PH + pb + o01) =
                        __floats2half2_rn(p0, p1);
                    int nf8 = nfl + 8;
                    uint32_t o23 = (uint32_t)(nf8 * 128 + ((u ^ (nf8 & 7)) << 4) + tm2 * 2);
                    *reinterpret_cast<__half2*>(smc + OFF_PH + pb + o23) =
                        __floats2half2_rn(p2, p3);
                }
            }
        }

        // ---- O(c-1): fp16 mma; warp = 32n x 32e over k = 64 m ----
        if (c > 0) {
            uint32_t pb = (uint32_t)(((c - 1) & 1) * 16384);
            uint32_t vb = (uint32_t)(((c - 1) & 1) * 8192);
            #pragma unroll
            for (int ks = 0; ks < 4; ++ks) {
                int un = ks * 2 + usub;
                uint32_t pH[2][4];
                #pragma unroll
                for (int i = 0; i < 2; ++i) {
                    uint32_t ra = swu(0, n0w + i * 16 + rowoff, un);
                    LDMX4(pH[i], sb + OFF_PH + pb + ra);
                }
                #pragma unroll
                for (int egl = 0; egl < 2; ++egl) {
                    int eg = wm * 2 + egl;
                    uint32_t va = swu(0, ks * 16 + rowoff, eg * 2 + usub);
                    uint32_t vv[4];
                    LDMX4_T(vv, sb + OFF_V + vb + va);
                    #pragma unroll
                    for (int i = 0; i < 2; ++i) {
                        MMA_F16(ofr[i][egl * 2],     pH[i], vv[0], vv[1]);
                        MMA_F16(ofr[i][egl * 2 + 1], pH[i], vv[2], vv[3]);
                    }
                }
            }
        }
    }

    // ---- Epilogue: direct per-warp stores, + bias ----
    float* ob = out + ((size_t)b * NN + n0) * DD;
    #pragma unroll
    for (int i = 0; i < 2; ++i) {
        int r = wn * 32 + i * 16 + t4;
        #pragma unroll
        for (int te = 0; te < 4; ++te) {
            int e = wm * 32 + te * 8 + tm2;
            float bj0 = bias[e], bj1 = bias[e + 1];
            *reinterpret_cast<float2*>(ob + (size_t)r * DD + e) =
                make_float2(ofr[i][te][0] + bj0, ofr[i][te][1] + bj1);
            *reinterpret_cast<float2*>(ob + (size_t)(r + 8) * DD + e) =
                make_float2(ofr[i][te][2] + bj0, ofr[i][te][3] + bj1);
        }
    }
}

// ---------------------------------------------------------------------------
extern "C" void kernel_launch(void* const* d_in, const int* in_sizes, int n_in,
                              void* d_out, int out_size) {
    const float* x    = (const float*)d_in[0];
    const float* w    = (const float*)d_in[1];
    const float* att  = (const float*)d_in[2];
    const float* bias = (const float*)d_in[3];
    const int*   mask = (const int*)d_in[4];
    float* out = (float*)d_out;

    prep_A<<<(NN * NN / 4) / 256, 256>>>(att, mask);
    prep_xw<<<(BB * NN) / 8, 256>>>(x, w);

    cudaFuncSetAttribute(fused, cudaFuncAttributeMaxDynamicSharedMemorySize, SMEM_BYTES);
    dim3 grid(NN / 128, BB);
    fused<<<grid, 256, SMEM_BYTES>>>(bias, out);
}

// round 15
// speedup vs baseline: 1.6312x; 1.1769x over previous
#include <cuda_runtime.h>
#include <cuda_bf16.h>
#include <cuda_fp16.h>
#include <cstdint>

#define BB 16
#define NN 2048
#define DD 64
// All 16-bit tiles: exact 128-byte rows, XOR swizzle (unit ^= row&7).

// ---------------- scratch (__device__ globals) -----------------------------
__device__ __half g_yh[BB * NN * DD];   // normalized x, fp16 hi
__device__ __half g_yl[BB * NN * DD];   // normalized x, fp16 lo
__device__ __half g_v[BB * NN * DD];    // support = x@W, fp16
__device__ float  g_A[NN * NN];         // att * mask

// ---------------- smem byte offsets (swizzled 128B-row tiles) --------------
#define OFF_YNH 0          // 128 x 128B                     16384
#define OFF_YNL 16384      //                                16384
#define OFF_YMH 32768      // 2 bufs x (64 x 128B)           16384
#define OFF_V   49152      // 2 bufs x (64 x 128B, fp16)     16384
#define OFF_PH  65536      // 2 bufs x (128 x 128B, fp16)    32768
#define SMEM_BYTES 98304

typedef unsigned long long ull;
__device__ __forceinline__ void unpk(ull v, float& lo, float& hi) {
    asm("mov.b64 {%0, %1}, %2;" : "=f"(lo), "=f"(hi) : "l"(v));
}
__device__ __forceinline__ uint32_t su32(const void* p) {
    uint32_t a;
    asm("{ .reg .u64 t; cvta.to.shared.u64 t, %1; cvt.u32.u64 %0, t; }" : "=r"(a) : "l"(p));
    return a;
}
__device__ __forceinline__ uint32_t swu(uint32_t base, int row, int unit) {
    return base + row * 128 + ((unit ^ (row & 7)) << 4);
}
__device__ __forceinline__ void cpa16(uint32_t dst, const void* src) {
    asm volatile("cp.async.cg.shared.global [%0], [%1], 16;" :: "r"(dst), "l"(src));
}
#define CPA_COMMIT() asm volatile("cp.async.commit_group;" ::: "memory")
#define CPA_WAIT(N)  asm volatile("cp.async.wait_group %0;" :: "n"(N) : "memory")

#define LDMX4(r, addr)                                                        \
    asm volatile("ldmatrix.sync.aligned.m8n8.x4.shared.b16 {%0,%1,%2,%3}, [%4];" \
        : "=r"((r)[0]), "=r"((r)[1]), "=r"((r)[2]), "=r"((r)[3]) : "r"(addr))
#define LDMX4_T(r, addr)                                                      \
    asm volatile("ldmatrix.sync.aligned.m8n8.x4.trans.shared.b16 {%0,%1,%2,%3}, [%4];" \
        : "=r"((r)[0]), "=r"((r)[1]), "=r"((r)[2]), "=r"((r)[3]) : "r"(addr))
#define MMA_F16(c, a, b0, b1)                                                 \
    asm volatile("mma.sync.aligned.m16n8k16.row.col.f32.f16.f16.f32 "         \
        "{%0,%1,%2,%3}, {%4,%5,%6,%7}, {%8,%9}, {%0,%1,%2,%3};"               \
        : "+f"((c)[0]), "+f"((c)[1]), "+f"((c)[2]), "+f"((c)[3])              \
        : "r"((a)[0]), "r"((a)[1]), "r"((a)[2]), "r"((a)[3]), "r"(b0), "r"(b1))

// ---------------------------------------------------------------------------
// Kernel A: A = att * mask
// ---------------------------------------------------------------------------
__global__ void prep_A(const float* __restrict__ att, const int* __restrict__ mask) {
    int i = blockIdx.x * blockDim.x + threadIdx.x;
    float4 a = reinterpret_cast<const float4*>(att)[i];
    int4   m = reinterpret_cast<const int4*>(mask)[i];
    float4 r;
    r.x = a.x * (float)m.x; r.y = a.y * (float)m.y;
    r.z = a.z * (float)m.z; r.w = a.w * (float)m.w;
    reinterpret_cast<float4*>(g_A)[i] = r;
}

// ---------------------------------------------------------------------------
// Kernel B: y = x/||x|| -> fp16 hi/lo ; v = x @ W -> fp16
// ---------------------------------------------------------------------------
__global__ void prep_xw(const float* __restrict__ x, const float* __restrict__ w) {
    __shared__ float sw[DD * DD];
    int tid = threadIdx.x;
    for (int i = tid; i < DD * DD; i += 256) sw[i] = w[i];
    __syncthreads();

    int warp = tid >> 5, lane = tid & 31;
    int row = blockIdx.x * 8 + warp;
    const float* xr = x + (size_t)row * DD;
    float x0 = xr[lane], x1 = xr[lane + 32];

    float ss = x0 * x0 + x1 * x1;
    #pragma unroll
    for (int o = 16; o; o >>= 1) ss += __shfl_xor_sync(0xffffffffu, ss, o);
    float inv = rsqrtf(fmaxf(ss, 1e-30f));

    float y0 = x0 * inv, y1 = x1 * inv;
    __half h0 = __float2half_rn(y0), h1 = __float2half_rn(y1);
    size_t rb = (size_t)row * DD;
    g_yh[rb + lane]      = h0;
    g_yh[rb + lane + 32] = h1;
    g_yl[rb + lane]      = __float2half_rn(y0 - __half2float(h0));
    g_yl[rb + lane + 32] = __float2half_rn(y1 - __half2float(h1));

    float a0 = 0.f, a1 = 0.f;
    #pragma unroll
    for (int d = 0; d < 32; ++d) {
        float xd = __shfl_sync(0xffffffffu, x0, d);
        a0 = fmaf(xd, sw[d * DD + lane],      a0);
        a1 = fmaf(xd, sw[d * DD + lane + 32], a1);
    }
    #pragma unroll
    for (int d = 0; d < 32; ++d) {
        float xd = __shfl_sync(0xffffffffu, x1, d);
        a0 = fmaf(xd, sw[(d + 32) * DD + lane],      a0);
        a1 = fmaf(xd, sw[(d + 32) * DD + lane + 32], a1);
    }
    g_v[rb + lane]      = __float2half_rn(a0);
    g_v[rb + lane + 32] = __float2half_rn(a1);
}

// ---------------------------------------------------------------------------
// Kernel C: 1-barrier pipelined: iter c does  B1 | stage(c+1) | S(c)+P(c) | O(c-1).
//   S = fp16 2-pass (YnH.YmH + YnL.YmH); P fp16 single; O fp16 single.
//   sP, V, YmH double-buffered. CTA = (b, 128n); 32 chunks of 64 m.
// ---------------------------------------------------------------------------
__global__ __launch_bounds__(256, 2)
void fused(const float* __restrict__ bias, float* __restrict__ out) {
    extern __shared__ char smc[];
    uint32_t sb = su32(smc);

    int b  = blockIdx.y;
    int n0 = blockIdx.x * 128;
    int tid = threadIdx.x;
    int w = tid >> 5, lane = tid & 31;
    int wn = w & 3, wm = w >> 2;
    int n0w = wn * 32, m0w = wm * 32;

    const __half* yhB = g_yh + (size_t)b * NN * DD;
    const __half* ylB = g_yl + (size_t)b * NN * DD;
    const __half* vB  = g_v  + (size_t)b * NN * DD;

    int sr_base = tid >> 3, sc = tid & 7;

    // Stage Yn tile (128 x 64 fp16 hi/lo), one-time, swizzled
    #pragma unroll
    for (int k = 0; k < 4; ++k) {
        int r = sr_base + k * 32;
        uint32_t dof = swu(0, r, sc);
        size_t gof = (size_t)(n0 + r) * DD + sc * 8;
        *reinterpret_cast<uint4*>(smc + OFF_YNH + dof) =
            *reinterpret_cast<const uint4*>(yhB + gof);
        *reinterpret_cast<uint4*>(smc + OFF_YNL + dof) =
            *reinterpret_cast<const uint4*>(ylB + gof);
    }

    // Prologue: async-stage YmH(0) into buf 0
    #pragma unroll
    for (int k = 0; k < 2; ++k) {
        int r = sr_base + k * 32;
        uint32_t dof = swu(0, r, sc);
        size_t gof = (size_t)r * DD + sc * 8;
        cpa16(sb + OFF_YMH + dof, yhB + gof);
    }
    CPA_COMMIT();

    // ldmatrix lane addressing
    int lrow = lane & 7, sub = lane >> 3;
    int rowoff = (sub & 1) * 8 + lrow;
    int usub   = sub >> 1;
    int t4 = lane >> 2, tm2 = (lane & 3) * 2;

    float ofr[2][4][4];            // O frags: [n16 group i][e8 tile][4]
    #pragma unroll
    for (int i = 0; i < 2; ++i)
        #pragma unroll
        for (int te = 0; te < 4; ++te)
            #pragma unroll
            for (int q = 0; q < 4; ++q) ofr[i][te][q] = 0.f;

    for (int c = 0; c <= 32; ++c) {
        int buf = c & 1;

        CPA_WAIT(0);          // group from iter c-1: YmH(c) + V(c-1)
        __syncthreads();

        // Stage YmH(c+1) into buf^1 and V(c) into Vbuf[c&1]
        if (c < 32) {
            #pragma unroll
            for (int k = 0; k < 2; ++k) {
                int r = sr_base + k * 32;
                uint32_t dof = swu(0, r, sc);
                if (c + 1 < 32) {
                    size_t gof = (size_t)((c + 1) * 64 + r) * DD + sc * 8;
                    cpa16(sb + OFF_YMH + (uint32_t)((buf ^ 1) * 8192) + dof, yhB + gof);
                }
                size_t gv = (size_t)(c * 64 + r) * DD + sc * 8;
                cpa16(sb + OFF_V + (uint32_t)(buf * 8192) + dof, vB + gv);
            }
            CPA_COMMIT();
        }

        // ---- S(c) + P(c) ----
        if (c < 32) {
            int m0 = c * 64;
            uint32_t bo = (uint32_t)(buf * 8192);

            float cfr[2][4][4];
            #pragma unroll
            for (int i = 0; i < 2; ++i)
                #pragma unroll
                for (int j = 0; j < 4; ++j)
                    #pragma unroll
                    for (int q = 0; q < 4; ++q) cfr[i][j][q] = 0.f;

            #pragma unroll
            for (int ks = 0; ks < 4; ++ks) {
                int un = ks * 2 + usub;
                uint32_t aH[2][4], aL[2][4];
                #pragma unroll
                for (int i = 0; i < 2; ++i) {
                    uint32_t ra = swu(0, n0w + i * 16 + rowoff, un);
                    LDMX4(aH[i], sb + OFF_YNH + ra);
                    LDMX4(aL[i], sb + OFF_YNL + ra);
                }
                #pragma unroll
                for (int j16 = 0; j16 < 2; ++j16) {
                    uint32_t rb2 = swu(0, m0w + j16 * 16 + rowoff, un);
                    uint32_t bH[4];
                    LDMX4(bH, sb + OFF_YMH + bo + rb2);
                    #pragma unroll
                    for (int i = 0; i < 2; ++i)
                        #pragma unroll
                        for (int par = 0; par < 2; ++par) {
                            int mt = j16 * 2 + par;
                            MMA_F16(cfr[i][mt], aH[i], bH[par], bH[par + 2]);
                            MMA_F16(cfr[i][mt], aL[i], bH[par], bH[par + 2]);
                        }
                }
            }

            // P = A*S -> fp16 into sPh buf
            uint32_t pb = (uint32_t)(buf * 16384);
            #pragma unroll
            for (int i = 0; i < 2; ++i) {
                #pragma unroll
                for (int mt = 0; mt < 4; ++mt) {
                    int nfl = n0w + i * 16 + t4;
                    int mfl = m0w + mt * 8 + tm2;
                    const float* ar = g_A + (size_t)(n0 + nfl) * NN + (m0 + mfl);
                    ull ap0 = *reinterpret_cast<const ull*>(ar);
                    ull ap1 = *reinterpret_cast<const ull*>(ar + 8 * NN);
                    float a0, a1, a2, a3;
                    unpk(ap0, a0, a1);
                    unpk(ap1, a2, a3);
                    float p0 = cfr[i][mt][0] * a0, p1 = cfr[i][mt][1] * a1;
                    float p2 = cfr[i][mt][2] * a2, p3 = cfr[i][mt][3] * a3;

                    int u = mfl >> 3;
                    uint32_t o01 = (uint32_t)(nfl * 128 + ((u ^ (nfl & 7)) << 4) + tm2 * 2);
                    *reinterpret_cast<__half2*>(smc + OFF_PH + pb + o01) =
                        __floats2half2_rn(p0, p1);
                    int nf8 = nfl + 8;
                    uint32_t o23 = (uint32_t)(nf8 * 128 + ((u ^ (nf8 & 7)) << 4) + tm2 * 2);
                    *reinterpret_cast<__half2*>(smc + OFF_PH + pb + o23) =
                        __floats2half2_rn(p2, p3);
                }
            }
        }

        // ---- O(c-1): fp16 mma; warp = 32n x 32e over k = 64 m ----
        if (c > 0) {
            uint32_t pb = (uint32_t)(((c - 1) & 1) * 16384);
            uint32_t vb = (uint32_t)(((c - 1) & 1) * 8192);
            #pragma unroll
            for (int ks = 0; ks < 4; ++ks) {
                int un = ks * 2 + usub;
                uint32_t pH[2][4];
                #pragma unroll
                for (int i = 0; i < 2; ++i) {
                    uint32_t ra = swu(0, n0w + i * 16 + rowoff, un);
                    LDMX4(pH[i], sb + OFF_PH + pb + ra);
                }
                #pragma unroll
                for (int egl = 0; egl < 2; ++egl) {
                    int eg = wm * 2 + egl;
                    uint32_t va = swu(0, ks * 16 + rowoff, eg * 2 + usub);
                    uint32_t vv[4];
                    LDMX4_T(vv, sb + OFF_V + vb + va);
                    #pragma unroll
                    for (int i = 0; i < 2; ++i) {
                        MMA_F16(ofr[i][egl * 2],     pH[i], vv[0], vv[1]);
                        MMA_F16(ofr[i][egl * 2 + 1], pH[i], vv[2], vv[3]);
                    }
                }
            }
        }
    }

    // ---- Epilogue: direct per-warp stores, + bias ----
    float* ob = out + ((size_t)b * NN + n0) * DD;
    #pragma unroll
    for (int i = 0; i < 2; ++i) {
        int r = wn * 32 + i * 16 + t4;
        #pragma unroll
        for (int te = 0; te < 4; ++te) {
            int e = wm * 32 + te * 8 + tm2;
            float bj0 = bias[e], bj1 = bias[e + 1];
            *reinterpret_cast<float2*>(ob + (size_t)r * DD + e) =
                make_float2(ofr[i][te][0] + bj0, ofr[i][te][1] + bj1);
            *reinterpret_cast<float2*>(ob + (size_t)(r + 8) * DD + e) =
                make_float2(ofr[i][te][2] + bj0, ofr[i][te][3] + bj1);
        }
    }
}

// ---------------------------------------------------------------------------
extern "C" void kernel_launch(void* const* d_in, const int* in_sizes, int n_in,
                              void* d_out, int out_size) {
    const float* x    = (const float*)d_in[0];
    const float* w    = (const float*)d_in[1];
    const float* att  = (const float*)d_in[2];
    const float* bias = (const float*)d_in[3];
    const int*   mask = (const int*)d_in[4];
    float* out = (float*)d_out;

    prep_A<<<(NN * NN / 4) / 256, 256>>>(att, mask);
    prep_xw<<<(BB * NN) / 8, 256>>>(x, w);

    cudaFuncSetAttribute(fused, cudaFuncAttributeMaxDynamicSharedMemorySize, SMEM_BYTES);
    dim3 grid(NN / 128, BB);
    fused<<<grid, 256, SMEM_BYTES>>>(bias, out);
}

// round 17
// speedup vs baseline: 1.8418x; 1.1291x over previous
#include <cuda_runtime.h>
#include <cuda_bf16.h>
#include <cuda_fp16.h>
#include <cstdint>

#define BB 16
#define NN 2048
#define DD 64
// All 16-bit tiles: exact 128-byte rows, XOR swizzle (unit ^= row&7).

// ---------------- scratch (__device__ globals) -----------------------------
__device__ __half g_y[BB * NN * DD];    // normalized x, fp16
__device__ __half g_v[BB * NN * DD];    // support = x@W, fp16
__device__ float  g_A[NN * NN];         // att * mask

// ---------------- smem byte offsets (swizzled 128B-row tiles) --------------
#define OFF_YN  0          // 128 x 128B                     16384
#define OFF_YM  16384      // 2 bufs x (64 x 128B)           16384
#define OFF_V   32768      // 2 bufs x (64 x 128B, fp16)     16384
#define OFF_PH  49152      // 2 bufs x (128 x 128B, fp16)    32768
#define SMEM_BYTES 81920

typedef unsigned long long ull;
__device__ __forceinline__ void unpk(ull v, float& lo, float& hi) {
    asm("mov.b64 {%0, %1}, %2;" : "=f"(lo), "=f"(hi) : "l"(v));
}
__device__ __forceinline__ uint32_t su32(const void* p) {
    uint32_t a;
    asm("{ .reg .u64 t; cvta.to.shared.u64 t, %1; cvt.u32.u64 %0, t; }" : "=r"(a) : "l"(p));
    return a;
}
__device__ __forceinline__ uint32_t swu(uint32_t base, int row, int unit) {
    return base + row * 128 + ((unit ^ (row & 7)) << 4);
}
__device__ __forceinline__ void cpa16(uint32_t dst, const void* src) {
    asm volatile("cp.async.cg.shared.global [%0], [%1], 16;" :: "r"(dst), "l"(src));
}
#define CPA_COMMIT() asm volatile("cp.async.commit_group;" ::: "memory")
#define CPA_WAIT(N)  asm volatile("cp.async.wait_group %0;" :: "n"(N) : "memory")

#define LDMX4(r, addr)                                                        \
    asm volatile("ldmatrix.sync.aligned.m8n8.x4.shared.b16 {%0,%1,%2,%3}, [%4];" \
        : "=r"((r)[0]), "=r"((r)[1]), "=r"((r)[2]), "=r"((r)[3]) : "r"(addr))
#define LDMX4_T(r, addr)                                                      \
    asm volatile("ldmatrix.sync.aligned.m8n8.x4.trans.shared.b16 {%0,%1,%2,%3}, [%4];" \
        : "=r"((r)[0]), "=r"((r)[1]), "=r"((r)[2]), "=r"((r)[3]) : "r"(addr))
#define MMA_F16(c, a, b0, b1)                                                 \
    asm volatile("mma.sync.aligned.m16n8k16.row.col.f32.f16.f16.f32 "         \
        "{%0,%1,%2,%3}, {%4,%5,%6,%7}, {%8,%9}, {%0,%1,%2,%3};"               \
        : "+f"((c)[0]), "+f"((c)[1]), "+f"((c)[2]), "+f"((c)[3])              \
        : "r"((a)[0]), "r"((a)[1]), "r"((a)[2]), "r"((a)[3]), "r"(b0), "r"(b1))

// ---------------------------------------------------------------------------
// Merged prep kernel: blocks [0,4096) do A = att*mask; [4096,8192) do xw.
// ---------------------------------------------------------------------------
__global__ void prep(const float* __restrict__ att, const int* __restrict__ mask,
                     const float* __restrict__ x, const float* __restrict__ w) {
    __shared__ float sw[DD * DD];
    int tid = threadIdx.x;

    if (blockIdx.x < 4096) {
        int i = blockIdx.x * 256 + tid;
        float4 a = reinterpret_cast<const float4*>(att)[i];
        int4   m = reinterpret_cast<const int4*>(mask)[i];
        float4 r;
        r.x = a.x * (float)m.x; r.y = a.y * (float)m.y;
        r.z = a.z * (float)m.z; r.w = a.w * (float)m.w;
        reinterpret_cast<float4*>(g_A)[i] = r;
        return;
    }

    for (int i = tid; i < DD * DD; i += 256) sw[i] = w[i];
    __syncthreads();

    int warp = tid >> 5, lane = tid & 31;
    int row = (blockIdx.x - 4096) * 8 + warp;
    const float* xr = x + (size_t)row * DD;
    float x0 = xr[lane], x1 = xr[lane + 32];

    float ss = x0 * x0 + x1 * x1;
    #pragma unroll
    for (int o = 16; o; o >>= 1) ss += __shfl_xor_sync(0xffffffffu, ss, o);
    float inv = rsqrtf(fmaxf(ss, 1e-30f));

    size_t rb = (size_t)row * DD;
    g_y[rb + lane]      = __float2half_rn(x0 * inv);
    g_y[rb + lane + 32] = __float2half_rn(x1 * inv);

    float a0 = 0.f, a1 = 0.f;
    #pragma unroll
    for (int d = 0; d < 32; ++d) {
        float xd = __shfl_sync(0xffffffffu, x0, d);
        a0 = fmaf(xd, sw[d * DD + lane],      a0);
        a1 = fmaf(xd, sw[d * DD + lane + 32], a1);
    }
    #pragma unroll
    for (int d = 0; d < 32; ++d) {
        float xd = __shfl_sync(0xffffffffu, x1, d);
        a0 = fmaf(xd, sw[(d + 32) * DD + lane],      a0);
        a1 = fmaf(xd, sw[(d + 32) * DD + lane + 32], a1);
    }
    g_v[rb + lane]      = __float2half_rn(a0);
    g_v[rb + lane + 32] = __float2half_rn(a1);
}

// ---------------------------------------------------------------------------
// Kernel C: 1-barrier pipelined: iter c does  B1 | stage(c+1) | S(c)+P(c) | O(c-1).
//   S = fp16 single-pass; P fp16 single; O fp16 single.
//   sP, V, Ym double-buffered. CTA = (b, 128n); 32 chunks of 64 m.
// ---------------------------------------------------------------------------
__global__ __launch_bounds__(256, 2)
void fused(const float* __restrict__ bias, float* __restrict__ out) {
    extern __shared__ char smc[];
    uint32_t sb = su32(smc);

    int b  = blockIdx.y;
    int n0 = blockIdx.x * 128;
    int tid = threadIdx.x;
    int w = tid >> 5, lane = tid & 31;
    int wn = w & 3, wm = w >> 2;
    int n0w = wn * 32, m0w = wm * 32;

    const __half* yB = g_y + (size_t)b * NN * DD;
    const __half* vB = g_v + (size_t)b * NN * DD;

    int sr_base = tid >> 3, sc = tid & 7;

    // Stage Yn tile (128 x 64 fp16), one-time, swizzled
    #pragma unroll
    for (int k = 0; k < 4; ++k) {
        int r = sr_base + k * 32;
        uint32_t dof = swu(0, r, sc);
        *reinterpret_cast<uint4*>(smc + OFF_YN + dof) =
            *reinterpret_cast<const uint4*>(yB + (size_t)(n0 + r) * DD + sc * 8);
    }

    // Prologue: async-stage Ym(0) into buf 0
    #pragma unroll
    for (int k = 0; k < 2; ++k) {
        int r = sr_base + k * 32;
        cpa16(sb + OFF_YM + swu(0, r, sc), yB + (size_t)r * DD + sc * 8);
    }
    CPA_COMMIT();

    // ldmatrix lane addressing
    int lrow = lane & 7, sub = lane >> 3;
    int rowoff = (sub & 1) * 8 + lrow;
    int usub   = sub >> 1;
    int t4 = lane >> 2, tm2 = (lane & 3) * 2;

    float ofr[2][4][4];            // O frags: [n16 group i][e8 tile][4]
    #pragma unroll
    for (int i = 0; i < 2; ++i)
        #pragma unroll
        for (int te = 0; te < 4; ++te)
            #pragma unroll
            for (int q = 0; q < 4; ++q) ofr[i][te][q] = 0.f;

    for (int c = 0; c <= 32; ++c) {
        int buf = c & 1;

        CPA_WAIT(0);          // group from iter c-1: Ym(c) + V(c-1)
        __syncthreads();

        // Stage Ym(c+1) into buf^1 and V(c) into Vbuf[c&1]
        if (c < 32) {
            #pragma unroll
            for (int k = 0; k < 2; ++k) {
                int r = sr_base + k * 32;
                uint32_t dof = swu(0, r, sc);
                if (c + 1 < 32) {
                    cpa16(sb + OFF_YM + (uint32_t)((buf ^ 1) * 8192) + dof,
                          yB + (size_t)((c + 1) * 64 + r) * DD + sc * 8);
                }
                cpa16(sb + OFF_V + (uint32_t)(buf * 8192) + dof,
                      vB + (size_t)(c * 64 + r) * DD + sc * 8);
            }
            CPA_COMMIT();
        }

        // ---- S(c) + P(c) ----
        if (c < 32) {
            int m0 = c * 64;
            uint32_t bo = (uint32_t)(buf * 8192);

            float cfr[2][4][4];
            #pragma unroll
            for (int i = 0; i < 2; ++i)
                #pragma unroll
                for (int j = 0; j < 4; ++j)
                    #pragma unroll
                    for (int q = 0; q < 4; ++q) cfr[i][j][q] = 0.f;

            #pragma unroll
            for (int ks = 0; ks < 4; ++ks) {
                int un = ks * 2 + usub;
                uint32_t aF[2][4];
                #pragma unroll
                for (int i = 0; i < 2; ++i) {
                    uint32_t ra = swu(0, n0w + i * 16 + rowoff, un);
                    LDMX4(aF[i], sb + OFF_YN + ra);
                }
                #pragma unroll
                for (int j16 = 0; j16 < 2; ++j16) {
                    uint32_t rb2 = swu(0, m0w + j16 * 16 + rowoff, un);
                    uint32_t bH[4];
                    LDMX4(bH, sb + OFF_YM + bo + rb2);
                    #pragma unroll
                    for (int i = 0; i < 2; ++i)
                        #pragma unroll
                        for (int par = 0; par < 2; ++par) {
                            int mt = j16 * 2 + par;
                            MMA_F16(cfr[i][mt], aF[i], bH[par], bH[par + 2]);
                        }
                }
            }

            // P = A*S -> fp16 into sPh buf
            uint32_t pb = (uint32_t)(buf * 16384);
            #pragma unroll
            for (int i = 0; i < 2; ++i) {
                #pragma unroll
                for (int mt = 0; mt < 4; ++mt) {
                    int nfl = n0w + i * 16 + t4;
                    int mfl = m0w + mt * 8 + tm2;
                    const float* ar = g_A + (size_t)(n0 + nfl) * NN + (m0 + mfl);
                    ull ap0 = *reinterpret_cast<const ull*>(ar);
                    ull ap1 = *reinterpret_cast<const ull*>(ar + 8 * NN);
                    float a0, a1, a2, a3;
                    unpk(ap0, a0, a1);
                    unpk(ap1, a2, a3);
                    float p0 = cfr[i][mt][0] * a0, p1 = cfr[i][mt][1] * a1;
                    float p2 = cfr[i][mt][2] * a2, p3 = cfr[i][mt][3] * a3;

                    int u = mfl >> 3;
                    uint32_t o01 = (uint32_t)(nfl * 128 + ((u ^ (nfl & 7)) << 4) + tm2 * 2);
                    *reinterpret_cast<__half2*>(smc + OFF_PH + pb + o01) =
                        __floats2half2_rn(p0, p1);
                    int nf8 = nfl + 8;
                    uint32_t o23 = (uint32_t)(nf8 * 128 + ((u ^ (nf8 & 7)) << 4) + tm2 * 2);
                    *reinterpret_cast<__half2*>(smc + OFF_PH + pb + o23) =
                        __floats2half2_rn(p2, p3);
                }
            }
        }

        // ---- O(c-1): fp16 mma; warp = 32n x 32e over k = 64 m ----
        if (c > 0) {
            uint32_t pb = (uint32_t)(((c - 1) & 1) * 16384);
            uint32_t vb = (uint32_t)(((c - 1) & 1) * 8192);
            #pragma unroll
            for (int ks = 0; ks < 4; ++ks) {
                int un = ks * 2 + usub;
                uint32_t pH[2][4];
                #pragma unroll
                for (int i = 0; i < 2; ++i) {
                    uint32_t ra = swu(0, n0w + i * 16 + rowoff, un);
                    LDMX4(pH[i], sb + OFF_PH + pb + ra);
                }
                #pragma unroll
                for (int egl = 0; egl < 2; ++egl) {
                    int eg = wm * 2 + egl;
                    uint32_t va = swu(0, ks * 16 + rowoff, eg * 2 + usub);
                    uint32_t vv[4];
                    LDMX4_T(vv, sb + OFF_V + vb + va);
                    #pragma unroll
                    for (int i = 0; i < 2; ++i) {
                        MMA_F16(ofr[i][egl * 2],     pH[i], vv[0], vv[1]);
                        MMA_F16(ofr[i][egl * 2 + 1], pH[i], vv[2], vv[3]);
                    }
                }
            }
        }
    }

    // ---- Epilogue: direct per-warp stores, + bias ----
    float* ob = out + ((size_t)b * NN + n0) * DD;
    #pragma unroll
    for (int i = 0; i < 2; ++i) {
        int r = wn * 32 + i * 16 + t4;
        #pragma unroll
        for (int te = 0; te < 4; ++te) {
            int e = wm * 32 + te * 8 + tm2;
            float bj0 = bias[e], bj1 = bias[e + 1];
            *reinterpret_cast<float2*>(ob + (size_t)r * DD + e) =
                make_float2(ofr[i][te][0] + bj0, ofr[i][te][1] + bj1);
            *reinterpret_cast<float2*>(ob + (size_t)(r + 8) * DD + e) =
                make_float2(ofr[i][te][2] + bj0, ofr[i][te][3] + bj1);
        }
    }
}

// ---------------------------------------------------------------------------
extern "C" void kernel_launch(void* const* d_in, const int* in_sizes, int n_in,
                              void* d_out, int out_size) {
    const float* x    = (const float*)d_in[0];
    const float* w    = (const float*)d_in[1];
    const float* att  = (const float*)d_in[2];
    const float* bias = (const float*)d_in[3];
    const int*   mask = (const int*)d_in[4];
    float* out = (float*)d_out;

    prep<<<8192, 256>>>(att, mask, x, w);

    cudaFuncSetAttribute(fused, cudaFuncAttributeMaxDynamicSharedMemorySize, SMEM_BYTES);
    dim3 grid(NN / 128, BB);
    fused<<<grid, 256, SMEM_BYTES>>>(bias, out);
}